// round 2
// baseline (speedup 1.0000x reference)
#include <cuda_runtime.h>
#include <cuda_bf16.h>

// Problem constants
#define N0   200000
#define N1   50000
#define N2C  10000
#define INF  602
#define HID  128
#define CLS  41
#define FAN  25

// Scratch for layer-1 activations: H1[N1][HID]  (25.6 MB, static device array)
__device__ float g_H1[N1 * HID];

// ---------------------------------------------------------------------------
// Kernel 1: H1[i][:] = relu( features[map1[i]] @ W1^T + b1 )
// Tiled SGEMM with fused row gather.
// BM=128 (rows), BN=128 (= HID, full), BK=8. 256 threads, 8x8 register tile.
// NOTE: map1 / neigh_idx arrive as int32 (JAX x64 disabled downcasts int64).
// ---------------------------------------------------------------------------
__global__ __launch_bounds__(256) void k_layer1(
    const float* __restrict__ features,
    const float* __restrict__ W1,      // [HID][INF] row-major
    const float* __restrict__ b1,      // [HID]
    const int* __restrict__ map1)      // [N1] int32
{
    __shared__ __align__(16) float As[8][132];   // [k][m], padded (132*4=528, 16B multiple)
    __shared__ __align__(16) float Bs[8][132];   // [k][h], padded

    const int tid = threadIdx.x;
    const int tx  = tid & 15;          // col group (hidden)
    const int ty  = tid >> 4;          // row group
    const int row0 = blockIdx.x * 128;

    // --- load-assignment: each thread loads 4 floats of one A row and 4 of one W1 row
    const int lr = tid >> 1;           // local row 0..127 (for both A and B loads)
    const int kp = (tid & 1) * 4;      // k sub-offset 0 or 4

    const int  grow   = row0 + lr;
    const bool rvalid = (grow < N1);
    int        src    = 0;
    if (rvalid) src = map1[grow];
    const float* arow = features + (size_t)src * INF;
    const float* wrow = W1 + (size_t)lr * INF;

    float acc[8][8];
    #pragma unroll
    for (int i = 0; i < 8; i++)
        #pragma unroll
        for (int j = 0; j < 8; j++) acc[i][j] = 0.f;

    for (int k0 = 0; k0 < INF; k0 += 8) {
        const int kg = k0 + kp;

        // ---- stage loads into registers (global) ----
        float a0 = 0.f, a1 = 0.f, a2 = 0.f, a3 = 0.f;
        if (rvalid) {
            if (kg + 3 < INF) {
                float2 v0 = *(const float2*)(arow + kg);
                float2 v1 = *(const float2*)(arow + kg + 2);
                a0 = v0.x; a1 = v0.y; a2 = v1.x; a3 = v1.y;
            } else {
                if (kg + 0 < INF) a0 = arow[kg + 0];
                if (kg + 1 < INF) a1 = arow[kg + 1];
                if (kg + 2 < INF) a2 = arow[kg + 2];
                if (kg + 3 < INF) a3 = arow[kg + 3];
            }
        }
        float w0 = 0.f, w1 = 0.f, w2 = 0.f, w3 = 0.f;
        if (kg + 3 < INF) {
            float2 v0 = *(const float2*)(wrow + kg);
            float2 v1 = *(const float2*)(wrow + kg + 2);
            w0 = v0.x; w1 = v0.y; w2 = v1.x; w3 = v1.y;
        } else {
            if (kg + 0 < INF) w0 = wrow[kg + 0];
            if (kg + 1 < INF) w1 = wrow[kg + 1];
            if (kg + 2 < INF) w2 = wrow[kg + 2];
            if (kg + 3 < INF) w3 = wrow[kg + 3];
        }

        __syncthreads();   // previous iteration's smem reads done
        As[kp + 0][lr] = a0;
        As[kp + 1][lr] = a1;
        As[kp + 2][lr] = a2;
        As[kp + 3][lr] = a3;
        Bs[kp + 0][lr] = w0;
        Bs[kp + 1][lr] = w1;
        Bs[kp + 2][lr] = w2;
        Bs[kp + 3][lr] = w3;
        __syncthreads();   // tiles ready

        // ---- compute 8x8 outer products over BK=8 ----
        #pragma unroll
        for (int kk = 0; kk < 8; kk++) {
            float4 av0 = *(const float4*)(&As[kk][ty * 8]);
            float4 av1 = *(const float4*)(&As[kk][ty * 8 + 4]);
            float4 bv0 = *(const float4*)(&Bs[kk][tx * 8]);
            float4 bv1 = *(const float4*)(&Bs[kk][tx * 8 + 4]);
            float a[8] = {av0.x, av0.y, av0.z, av0.w, av1.x, av1.y, av1.z, av1.w};
            float b[8] = {bv0.x, bv0.y, bv0.z, bv0.w, bv1.x, bv1.y, bv1.z, bv1.w};
            #pragma unroll
            for (int i = 0; i < 8; i++)
                #pragma unroll
                for (int j = 0; j < 8; j++)
                    acc[i][j] = fmaf(a[i], b[j], acc[i][j]);
        }
    }

    // ---- epilogue: bias + relu, write H1 ----
    const int c0 = tx * 8;
    float bias[8];
    #pragma unroll
    for (int j = 0; j < 8; j++) bias[j] = b1[c0 + j];

    #pragma unroll
    for (int i = 0; i < 8; i++) {
        const int r = row0 + ty * 8 + i;
        if (r < N1) {
            float4 o0, o1;
            float v;
            v = acc[i][0] + bias[0]; o0.x = v > 0.f ? v : 0.f;
            v = acc[i][1] + bias[1]; o0.y = v > 0.f ? v : 0.f;
            v = acc[i][2] + bias[2]; o0.z = v > 0.f ? v : 0.f;
            v = acc[i][3] + bias[3]; o0.w = v > 0.f ? v : 0.f;
            v = acc[i][4] + bias[4]; o1.x = v > 0.f ? v : 0.f;
            v = acc[i][5] + bias[5]; o1.y = v > 0.f ? v : 0.f;
            v = acc[i][6] + bias[6]; o1.z = v > 0.f ? v : 0.f;
            v = acc[i][7] + bias[7]; o1.w = v > 0.f ? v : 0.f;
            *(float4*)(&g_H1[(size_t)r * HID + c0])     = o0;
            *(float4*)(&g_H1[(size_t)r * HID + c0 + 4]) = o1;
        }
    }
}

// ---------------------------------------------------------------------------
// Kernel 2: per seed node, mean of 25 H1 rows, then @ W2^T + b2 -> [N2][CLS]
// One block (128 threads) per seed node.
// ---------------------------------------------------------------------------
__global__ __launch_bounds__(128) void k_layer2(
    const int* __restrict__ neigh,         // [N2][FAN] int32
    const float* __restrict__ W2,          // [CLS][HID]
    const float* __restrict__ b2,          // [CLS]
    float* __restrict__ out)               // [N2][CLS]
{
    __shared__ float agg[HID];
    const int n   = blockIdx.x;
    const int tid = threadIdx.x;

    const int* nb = neigh + (size_t)n * FAN;
    float s = 0.f;
    #pragma unroll
    for (int j = 0; j < FAN; j++) {
        int idx = nb[j];                       // uniform across block -> broadcast
        s += g_H1[(size_t)idx * HID + tid];    // coalesced 512B row reads (L2-hot)
    }
    agg[tid] = s * (1.0f / FAN);
    __syncthreads();

    if (tid < CLS) {
        float accv = b2[tid];
        const float* w = W2 + (size_t)tid * HID;
        #pragma unroll 8
        for (int h = 0; h < HID; h++)
            accv = fmaf(agg[h], w[h], accv);
        out[(size_t)n * CLS + tid] = accv;
    }
}

// ---------------------------------------------------------------------------
// Launch
// Inputs (metadata order): features f32, W1 f32, b1 f32, W2 f32, b2 f32,
//                          map1 i32, neigh_idx i32.  Output: f32 [N2*CLS].
// ---------------------------------------------------------------------------
extern "C" void kernel_launch(void* const* d_in, const int* in_sizes, int n_in,
                              void* d_out, int out_size) {
    const float* features = (const float*)d_in[0];
    const float* W1       = (const float*)d_in[1];
    const float* b1       = (const float*)d_in[2];
    const float* W2       = (const float*)d_in[3];
    const float* b2       = (const float*)d_in[4];
    const int*   map1     = (const int*)d_in[5];
    const int*   neigh    = (const int*)d_in[6];
    float*       out      = (float*)d_out;

    const int grid1 = (N1 + 127) / 128;   // 391
    k_layer1<<<grid1, 256>>>(features, W1, b1, map1);
    k_layer2<<<N2C, 128>>>(neigh, W2, b2, out);
}

// round 4
// speedup vs baseline: 1.2416x; 1.2416x over previous
#include <cuda_runtime.h>
#include <cuda_bf16.h>

// Problem constants
#define N0   200000
#define N1   50000
#define N2C  10000
#define INF  602
#define HID  128
#define CLS  41
#define FAN  25

// Scratch: H1[N1][HID] (25.6 MB) and per-node logits G[N1][CLS] (8.2 MB)
__device__ float g_H1[N1 * HID];
__device__ float g_G [N1 * CLS];

// ---------------------------------------------------------------------------
// Kernel 1: H1[i][:] = relu( features[map1[i]] @ W1^T + b1 )
// Tiled SGEMM with fused row gather. (unchanged from R2 — known good)
// ---------------------------------------------------------------------------
__global__ __launch_bounds__(256) void k_layer1(
    const float* __restrict__ features,
    const float* __restrict__ W1,      // [HID][INF] row-major
    const float* __restrict__ b1,      // [HID]
    const int* __restrict__ map1)      // [N1] int32
{
    __shared__ __align__(16) float As[8][132];
    __shared__ __align__(16) float Bs[8][132];

    const int tid = threadIdx.x;
    const int tx  = tid & 15;
    const int ty  = tid >> 4;
    const int row0 = blockIdx.x * 128;

    const int lr = tid >> 1;
    const int kp = (tid & 1) * 4;

    const int  grow   = row0 + lr;
    const bool rvalid = (grow < N1);
    int        src    = 0;
    if (rvalid) src = map1[grow];
    const float* arow = features + (size_t)src * INF;
    const float* wrow = W1 + (size_t)lr * INF;

    float acc[8][8];
    #pragma unroll
    for (int i = 0; i < 8; i++)
        #pragma unroll
        for (int j = 0; j < 8; j++) acc[i][j] = 0.f;

    for (int k0 = 0; k0 < INF; k0 += 8) {
        const int kg = k0 + kp;

        float a0 = 0.f, a1 = 0.f, a2 = 0.f, a3 = 0.f;
        if (rvalid) {
            if (kg + 3 < INF) {
                float2 v0 = *(const float2*)(arow + kg);
                float2 v1 = *(const float2*)(arow + kg + 2);
                a0 = v0.x; a1 = v0.y; a2 = v1.x; a3 = v1.y;
            } else {
                if (kg + 0 < INF) a0 = arow[kg + 0];
                if (kg + 1 < INF) a1 = arow[kg + 1];
                if (kg + 2 < INF) a2 = arow[kg + 2];
                if (kg + 3 < INF) a3 = arow[kg + 3];
            }
        }
        float w0 = 0.f, w1 = 0.f, w2 = 0.f, w3 = 0.f;
        if (kg + 3 < INF) {
            float2 v0 = *(const float2*)(wrow + kg);
            float2 v1 = *(const float2*)(wrow + kg + 2);
            w0 = v0.x; w1 = v0.y; w2 = v1.x; w3 = v1.y;
        } else {
            if (kg + 0 < INF) w0 = wrow[kg + 0];
            if (kg + 1 < INF) w1 = wrow[kg + 1];
            if (kg + 2 < INF) w2 = wrow[kg + 2];
            if (kg + 3 < INF) w3 = wrow[kg + 3];
        }

        __syncthreads();
        As[kp + 0][lr] = a0;
        As[kp + 1][lr] = a1;
        As[kp + 2][lr] = a2;
        As[kp + 3][lr] = a3;
        Bs[kp + 0][lr] = w0;
        Bs[kp + 1][lr] = w1;
        Bs[kp + 2][lr] = w2;
        Bs[kp + 3][lr] = w3;
        __syncthreads();

        #pragma unroll
        for (int kk = 0; kk < 8; kk++) {
            float4 av0 = *(const float4*)(&As[kk][ty * 8]);
            float4 av1 = *(const float4*)(&As[kk][ty * 8 + 4]);
            float4 bv0 = *(const float4*)(&Bs[kk][tx * 8]);
            float4 bv1 = *(const float4*)(&Bs[kk][tx * 8 + 4]);
            float a[8] = {av0.x, av0.y, av0.z, av0.w, av1.x, av1.y, av1.z, av1.w};
            float b[8] = {bv0.x, bv0.y, bv0.z, bv0.w, bv1.x, bv1.y, bv1.z, bv1.w};
            #pragma unroll
            for (int i = 0; i < 8; i++)
                #pragma unroll
                for (int j = 0; j < 8; j++)
                    acc[i][j] = fmaf(a[i], b[j], acc[i][j]);
        }
    }

    const int c0 = tx * 8;
    float bias[8];
    #pragma unroll
    for (int j = 0; j < 8; j++) bias[j] = b1[c0 + j];

    #pragma unroll
    for (int i = 0; i < 8; i++) {
        const int r = row0 + ty * 8 + i;
        if (r < N1) {
            float4 o0, o1;
            float v;
            v = acc[i][0] + bias[0]; o0.x = v > 0.f ? v : 0.f;
            v = acc[i][1] + bias[1]; o0.y = v > 0.f ? v : 0.f;
            v = acc[i][2] + bias[2]; o0.z = v > 0.f ? v : 0.f;
            v = acc[i][3] + bias[3]; o0.w = v > 0.f ? v : 0.f;
            v = acc[i][4] + bias[4]; o1.x = v > 0.f ? v : 0.f;
            v = acc[i][5] + bias[5]; o1.y = v > 0.f ? v : 0.f;
            v = acc[i][6] + bias[6]; o1.z = v > 0.f ? v : 0.f;
            v = acc[i][7] + bias[7]; o1.w = v > 0.f ? v : 0.f;
            *(float4*)(&g_H1[(size_t)r * HID + c0])     = o0;
            *(float4*)(&g_H1[(size_t)r * HID + c0 + 4]) = o1;
        }
    }
}

// ---------------------------------------------------------------------------
// Kernel 2: per-node logits  G[r][c] = dot(H1[r], W2[c])   (no bias)
// Block = 256 threads, 64 rows per block. H1 tile + full W2 in smem.
// W2 smem padded to stride 129 -> conflict-free (129 mod 32 == 1).
// ---------------------------------------------------------------------------
#define LGR 64   // rows per block
__global__ __launch_bounds__(256) void k_logits(
    const float* __restrict__ W2)          // [CLS][HID]
{
    __shared__ __align__(16) float H1s[LGR][HID];
    __shared__ float W2s[CLS][129];

    const int tid  = threadIdx.x;
    const int row0 = blockIdx.x * LGR;

    // load W2 into smem (5248 floats)
    for (int i = tid; i < CLS * HID; i += 256)
        W2s[i / HID][i % HID] = W2[i];

    // load 64 H1 rows (8192 floats = 2048 float4)
    {
        const float4* src = (const float4*)&g_H1[(size_t)row0 * HID];
        float4* dst = (float4*)&H1s[0][0];
        const int nvec = LGR * HID / 4;          // 2048
        const int maxv = (N1 - row0) * (HID / 4); // guard for tail block
        for (int i = tid; i < nvec; i += 256) {
            float4 v = (i < maxv) ? src[i] : make_float4(0.f, 0.f, 0.f, 0.f);
            dst[i] = v;
        }
    }
    __syncthreads();

    // each thread: strided (row, class) outputs
    for (int idx = tid; idx < LGR * CLS; idx += 256) {
        const int r = idx / CLS;
        const int c = idx % CLS;
        const int gr = row0 + r;
        if (gr >= N1) break;
        float acc = 0.f;
        #pragma unroll 16
        for (int h = 0; h < HID; h++)
            acc = fmaf(H1s[r][h], W2s[c][h], acc);
        g_G[(size_t)gr * CLS + c] = acc;
    }
}

// ---------------------------------------------------------------------------
// Kernel 3: out[n][c] = b2[c] + mean_j G[neigh[n][j]][c]
// 4 seeds per block (64 threads each, 41 active). Coalesced 164B row reads.
// ---------------------------------------------------------------------------
__global__ __launch_bounds__(256) void k_gather(
    const int* __restrict__ neigh,         // [N2][FAN] int32
    const float* __restrict__ b2,          // [CLS]
    float* __restrict__ out)               // [N2][CLS]
{
    const int tid  = threadIdx.x;
    const int grp  = tid >> 6;             // 0..3
    const int lane = tid & 63;
    const int n    = blockIdx.x * 4 + grp;
    if (n >= N2C || lane >= CLS) return;

    const int* nb = neigh + (size_t)n * FAN;
    float s = 0.f;
    #pragma unroll
    for (int j = 0; j < FAN; j++) {
        int idx = nb[j];                   // uniform in group -> broadcast
        s += g_G[(size_t)idx * CLS + lane];
    }
    out[(size_t)n * CLS + lane] = fmaf(s, 1.0f / FAN, b2[lane]);
}

// ---------------------------------------------------------------------------
// Launch.  Inputs: features f32, W1 f32, b1 f32, W2 f32, b2 f32,
//                  map1 i32, neigh_idx i32.  Output: f32 [N2*CLS].
// ---------------------------------------------------------------------------
extern "C" void kernel_launch(void* const* d_in, const int* in_sizes, int n_in,
                              void* d_out, int out_size) {
    const float* features = (const float*)d_in[0];
    const float* W1       = (const float*)d_in[1];
    const float* b1       = (const float*)d_in[2];
    const float* W2       = (const float*)d_in[3];
    const float* b2       = (const float*)d_in[4];
    const int*   map1     = (const int*)d_in[5];
    const int*   neigh    = (const int*)d_in[6];
    float*       out      = (float*)d_out;

    const int grid1 = (N1 + 127) / 128;        // 391
    k_layer1<<<grid1, 256>>>(features, W1, b1, map1);

    const int grid2 = (N1 + LGR - 1) / LGR;    // 782
    k_logits<<<grid2, 256>>>(W2);

    const int grid3 = (N2C + 3) / 4;           // 2500
    k_gather<<<grid3, 256>>>(neigh, b2, out);
}

// round 6
// speedup vs baseline: 1.6250x; 1.3088x over previous
#include <cuda_runtime.h>
#include <cuda_bf16.h>
#include <cstdint>

// Problem constants
#define N0    200000
#define N1    50000
#define N2C   10000
#define INF   602
#define HID   128
#define CLS   41
#define CLSP  44      // padded classes (multiple of 4)
#define FAN   25

#define KSTEPS 38     // 38*16 = 608 >= 602 (zero-padded K)
#define APITCH 12     // uint32 (bf16-pair) pitch per row = 24 bf16 -> conflict-free frags

// Scratch: H1[N1][HID] (25.6 MB) and padded logits G[N1][CLSP] (8.8 MB)
__device__ float g_H1[N1 * HID];
__device__ float g_G [N1 * CLSP];

// ---------------------------------------------------------------------------
// MMA helper: D += A(bf16) * B(bf16), m16n8k16, fp32 accum
// ---------------------------------------------------------------------------
__device__ __forceinline__ void mma_bf16(float c[4],
                                         uint32_t a0, uint32_t a1, uint32_t a2, uint32_t a3,
                                         uint32_t b0, uint32_t b1)
{
    asm volatile(
        "mma.sync.aligned.m16n8k16.row.col.f32.bf16.bf16.f32 "
        "{%0,%1,%2,%3}, {%4,%5,%6,%7}, {%8,%9}, {%0,%1,%2,%3};\n"
        : "+f"(c[0]), "+f"(c[1]), "+f"(c[2]), "+f"(c[3])
        : "r"(a0), "r"(a1), "r"(a2), "r"(a3), "r"(b0), "r"(b1));
}

// ---------------------------------------------------------------------------
// Kernel 1: H1[r] = relu( features[map1[r]] @ W1^T + b1 )
// Tensor-core GEMM, bf16 hi/lo split (3 MMA terms -> ~fp32 accuracy).
// Block: 256 thr / 8 warps. BM=128 (16 rows/warp), BN=128, BK=16, double-buffered.
// NOTE: feature/W1 rows are 602 floats = 2408 B (8 mod 16) -> only float2
//       (8B) global loads are legal; float4 would trap on odd rows.
// ---------------------------------------------------------------------------
__global__ __launch_bounds__(256) void k_layer1(
    const float* __restrict__ features,
    const float* __restrict__ W1,      // [HID][INF]
    const float* __restrict__ b1,      // [HID]
    const int* __restrict__ map1)      // [N1] int32
{
    // 4 arrays x 2 buffers x 128 rows x 12 u32 = 49152 B (static smem limit exactly)
    __shared__ uint32_t Ah[2][128 * APITCH];
    __shared__ uint32_t Al[2][128 * APITCH];
    __shared__ uint32_t Bh[2][128 * APITCH];
    __shared__ uint32_t Bl[2][128 * APITCH];

    const int tid  = threadIdx.x;
    const int warp = tid >> 5;
    const int lane = tid & 31;
    const int g    = lane >> 2;        // 0..7
    const int i4   = lane & 3;         // 0..3

    const int row0 = blockIdx.x * 128;

    // staging assignment: 2 threads per row, 8 k-floats each
    const int lr = tid >> 1;           // 0..127
    const int kh = (tid & 1) * 8;      // 0 or 8
    const int sidx = lr * APITCH + (kh >> 1);   // pair index base in smem

    const int  grow   = row0 + lr;
    const bool rvalid = (grow < N1);
    const int  src    = rvalid ? map1[grow] : 0;
    const float* arow = features + (size_t)src * INF;
    const float* wrow = W1 + (size_t)lr * INF;

    float acc[16][4];
    #pragma unroll
    for (int t = 0; t < 16; t++)
        #pragma unroll
        for (int j = 0; j < 4; j++) acc[t][j] = 0.f;

    float sa[8], sb[8];

    // ---- stage loaders (float2 = 8B aligned for any row) ----
    auto load_regs = [&](int k0) {
        #pragma unroll
        for (int j = 0; j < 8; j += 2) {
            const int k = k0 + kh + j;      // always even
            if (k + 1 < INF) {
                if (rvalid) {
                    float2 v = *(const float2*)(arow + k);
                    sa[j] = v.x; sa[j+1] = v.y;
                } else {
                    sa[j] = 0.f; sa[j+1] = 0.f;
                }
                float2 w = *(const float2*)(wrow + k);
                sb[j] = w.x; sb[j+1] = w.y;
            } else {
                sa[j]   = (rvalid && k     < INF) ? arow[k]     : 0.f;
                sa[j+1] = (rvalid && k + 1 < INF) ? arow[k + 1] : 0.f;
                sb[j]   = (k     < INF) ? wrow[k]     : 0.f;
                sb[j+1] = (k + 1 < INF) ? wrow[k + 1] : 0.f;
            }
        }
    };

    auto store_stage = [&](int b) {
        #pragma unroll
        for (int j = 0; j < 4; j++) {
            // A hi/lo
            {
                float x0 = sa[2*j], x1 = sa[2*j+1];
                __nv_bfloat162 h2 = __floats2bfloat162_rn(x0, x1);
                float2 hf = __bfloat1622float2(h2);
                __nv_bfloat162 l2 = __floats2bfloat162_rn(x0 - hf.x, x1 - hf.y);
                Ah[b][sidx + j] = *reinterpret_cast<uint32_t*>(&h2);
                Al[b][sidx + j] = *reinterpret_cast<uint32_t*>(&l2);
            }
            // B hi/lo
            {
                float x0 = sb[2*j], x1 = sb[2*j+1];
                __nv_bfloat162 h2 = __floats2bfloat162_rn(x0, x1);
                float2 hf = __bfloat1622float2(h2);
                __nv_bfloat162 l2 = __floats2bfloat162_rn(x0 - hf.x, x1 - hf.y);
                Bh[b][sidx + j] = *reinterpret_cast<uint32_t*>(&h2);
                Bl[b][sidx + j] = *reinterpret_cast<uint32_t*>(&l2);
            }
        }
    };

    // ---- prologue ----
    load_regs(0);
    store_stage(0);
    __syncthreads();

    const int ra = (warp * 16 + g) * APITCH;

    // ---- main loop: one k16 step per stage ----
    #pragma unroll 1
    for (int s = 0; s < KSTEPS; s++) {
        if (s + 1 < KSTEPS) load_regs((s + 1) * 16);

        const int b = s & 1;
        // A fragments (hi & lo)
        uint32_t ah0 = Ah[b][ra + i4];
        uint32_t ah1 = Ah[b][ra + 8 * APITCH + i4];
        uint32_t ah2 = Ah[b][ra + i4 + 4];
        uint32_t ah3 = Ah[b][ra + 8 * APITCH + i4 + 4];
        uint32_t al0 = Al[b][ra + i4];
        uint32_t al1 = Al[b][ra + 8 * APITCH + i4];
        uint32_t al2 = Al[b][ra + i4 + 4];
        uint32_t al3 = Al[b][ra + 8 * APITCH + i4 + 4];

        #pragma unroll
        for (int nt = 0; nt < 16; nt++) {
            const int rb = (nt * 8 + g) * APITCH;
            uint32_t b0h = Bh[b][rb + i4];
            uint32_t b1h = Bh[b][rb + i4 + 4];
            uint32_t b0l = Bl[b][rb + i4];
            uint32_t b1l = Bl[b][rb + i4 + 4];
            mma_bf16(acc[nt], ah0, ah1, ah2, ah3, b0h, b1h);  // hi*hi
            mma_bf16(acc[nt], ah0, ah1, ah2, ah3, b0l, b1l);  // hi*lo
            mma_bf16(acc[nt], al0, al1, al2, al3, b0h, b1h);  // lo*hi
        }

        if (s + 1 < KSTEPS) store_stage((s + 1) & 1);
        __syncthreads();
    }

    // ---- epilogue: bias + relu -> g_H1 ----
    const int r0g = row0 + warp * 16 + g;
    const int r1g = r0g + 8;
    #pragma unroll
    for (int nt = 0; nt < 16; nt++) {
        const int col = nt * 8 + 2 * i4;
        const float bb0 = b1[col], bb1 = b1[col + 1];
        if (r0g < N1) {
            float v0 = acc[nt][0] + bb0, v1 = acc[nt][1] + bb1;
            float2 o = make_float2(v0 > 0.f ? v0 : 0.f, v1 > 0.f ? v1 : 0.f);
            *(float2*)(&g_H1[(size_t)r0g * HID + col]) = o;
        }
        if (r1g < N1) {
            float v0 = acc[nt][2] + bb0, v1 = acc[nt][3] + bb1;
            float2 o = make_float2(v0 > 0.f ? v0 : 0.f, v1 > 0.f ? v1 : 0.f);
            *(float2*)(&g_H1[(size_t)r1g * HID + col]) = o;
        }
    }
}

// ---------------------------------------------------------------------------
// Kernel 2: G[r][c] = dot(H1[r], W2[c]), c padded to 44. float4 vectorized.
// Block: 256 threads, 32 rows.
// ---------------------------------------------------------------------------
#define LGR 32
__global__ __launch_bounds__(256) void k_logits(
    const float* __restrict__ W2)          // [CLS][HID]
{
    __shared__ float4 H1s[LGR][HID / 4];   // 16 KB
    __shared__ float4 W2s[CLSP][33];       // 23.2 KB (pad stride 33)

    const int tid  = threadIdx.x;
    const int row0 = blockIdx.x * LGR;

    // load W2 (zero for padded classes); W2 rows are 128 floats -> float4 safe
    const float4* W24 = (const float4*)W2;
    for (int idx = tid; idx < CLSP * 32; idx += 256) {
        const int c = idx >> 5, h = idx & 31;
        W2s[c][h] = (c < CLS) ? W24[c * 32 + h] : make_float4(0.f, 0.f, 0.f, 0.f);
    }
    // load H1 rows (g_H1 rows are 512B -> float4 safe)
    {
        const float4* H14 = (const float4*)&g_H1[(size_t)row0 * HID];
        const int maxv = (N1 - row0) * 32;
        for (int idx = tid; idx < LGR * 32; idx += 256) {
            H1s[idx >> 5][idx & 31] =
                (idx < maxv) ? H14[idx] : make_float4(0.f, 0.f, 0.f, 0.f);
        }
    }
    __syncthreads();

    // tasks: (row, class-quad): 32 * 11 = 352
    for (int idx = tid; idx < LGR * (CLSP / 4); idx += 256) {
        const int r = idx / (CLSP / 4);
        const int q = idx % (CLSP / 4);
        const int gr = row0 + r;
        if (gr >= N1) continue;

        float a0 = 0.f, a1 = 0.f, a2 = 0.f, a3 = 0.f;
        #pragma unroll 8
        for (int h = 0; h < 32; h++) {
            float4 hv = H1s[r][h];
            float4 w0 = W2s[4*q + 0][h];
            float4 w1 = W2s[4*q + 1][h];
            float4 w2 = W2s[4*q + 2][h];
            float4 w3 = W2s[4*q + 3][h];
            a0 += hv.x*w0.x + hv.y*w0.y + hv.z*w0.z + hv.w*w0.w;
            a1 += hv.x*w1.x + hv.y*w1.y + hv.z*w1.z + hv.w*w1.w;
            a2 += hv.x*w2.x + hv.y*w2.y + hv.z*w2.z + hv.w*w2.w;
            a3 += hv.x*w3.x + hv.y*w3.y + hv.z*w3.z + hv.w*w3.w;
        }
        float4 o = make_float4(a0, a1, a2, a3);
        *(float4*)(&g_G[(size_t)gr * CLSP + 4*q]) = o;  // 176B rows, 16B-aligned
    }
}

// ---------------------------------------------------------------------------
// Kernel 3: out[n][c] = b2[c] + mean_j G[neigh[n][j]][c]
// 4 seeds per block of 256 (64-lane groups, 41 active lanes).
// ---------------------------------------------------------------------------
__global__ __launch_bounds__(256) void k_gather(
    const int* __restrict__ neigh,         // [N2][FAN] int32
    const float* __restrict__ b2,          // [CLS]
    float* __restrict__ out)               // [N2][CLS]
{
    const int tid  = threadIdx.x;
    const int grp  = tid >> 6;
    const int lane = tid & 63;
    const int n    = blockIdx.x * 4 + grp;
    if (n >= N2C || lane >= CLS) return;

    const int* nb = neigh + (size_t)n * FAN;
    float s = 0.f;
    #pragma unroll
    for (int j = 0; j < FAN; j++) {
        int idx = nb[j];
        s += g_G[(size_t)idx * CLSP + lane];
    }
    out[(size_t)n * CLS + lane] = fmaf(s, 1.0f / FAN, b2[lane]);
}

// ---------------------------------------------------------------------------
// Launch.  Inputs: features f32, W1 f32, b1 f32, W2 f32, b2 f32,
//                  map1 i32, neigh_idx i32.  Output: f32 [N2*CLS].
// ---------------------------------------------------------------------------
extern "C" void kernel_launch(void* const* d_in, const int* in_sizes, int n_in,
                              void* d_out, int out_size) {
    const float* features = (const float*)d_in[0];
    const float* W1       = (const float*)d_in[1];
    const float* b1       = (const float*)d_in[2];
    const float* W2       = (const float*)d_in[3];
    const float* b2       = (const float*)d_in[4];
    const int*   map1     = (const int*)d_in[5];
    const int*   neigh    = (const int*)d_in[6];
    float*       out      = (float*)d_out;

    const int grid1 = (N1 + 127) / 128;        // 391
    k_layer1<<<grid1, 256>>>(features, W1, b1, map1);

    const int grid2 = (N1 + LGR - 1) / LGR;    // 1563
    k_logits<<<grid2, 256>>>(W2);

    const int grid3 = (N2C + 3) / 4;           // 2500
    k_gather<<<grid3, 256>>>(neigh, b2, out);
}

// round 7
// speedup vs baseline: 2.9090x; 1.7901x over previous
#include <cuda_runtime.h>
#include <cuda_bf16.h>
#include <cstdint>

// Problem constants
#define N0    200000
#define N1    50000
#define N2C   10000
#define INF   602
#define HID   128
#define CLS   41
#define CLSP  44      // padded classes (multiple of 4)
#define FAN   25

#define KSTEPS 38     // 38*16 = 608 >= 602 (zero-padded K)
#define APITCH 12     // uint32 (bf16-pair) pitch per row -> conflict-free frags

// Scratch: H1[N1][HID] (25.6 MB) and padded logits G[N1][CLSP] (8.8 MB)
__device__ float g_H1[N1 * HID];
__device__ float g_G [N1 * CLSP];

// ---------------------------------------------------------------------------
// MMA helper: D += A(bf16) * B(bf16), m16n8k16, fp32 accum
// ---------------------------------------------------------------------------
__device__ __forceinline__ void mma_bf16(float c[4],
                                         uint32_t a0, uint32_t a1, uint32_t a2, uint32_t a3,
                                         uint32_t b0, uint32_t b1)
{
    asm volatile(
        "mma.sync.aligned.m16n8k16.row.col.f32.bf16.bf16.f32 "
        "{%0,%1,%2,%3}, {%4,%5,%6,%7}, {%8,%9}, {%0,%1,%2,%3};\n"
        : "+f"(c[0]), "+f"(c[1]), "+f"(c[2]), "+f"(c[3])
        : "r"(a0), "r"(a1), "r"(a2), "r"(a3), "r"(b0), "r"(b1));
}

__device__ __forceinline__ void split_pair(float x0, float x1,
                                           uint32_t& hi, uint32_t& lo)
{
    __nv_bfloat162 h2 = __floats2bfloat162_rn(x0, x1);
    float2 hf = __bfloat1622float2(h2);
    __nv_bfloat162 l2 = __floats2bfloat162_rn(x0 - hf.x, x1 - hf.y);
    hi = *reinterpret_cast<uint32_t*>(&h2);
    lo = *reinterpret_cast<uint32_t*>(&l2);
}

// ---------------------------------------------------------------------------
// Kernel 1: H1[r] = relu( features[map1[r]] @ W1^T + b1 )
// Tensor-core GEMM, bf16 hi/lo split (3 MMA terms -> ~fp32 accuracy).
// (unchanged from R6 — known good at 146us)
// ---------------------------------------------------------------------------
__global__ __launch_bounds__(256) void k_layer1(
    const float* __restrict__ features,
    const float* __restrict__ W1,      // [HID][INF]
    const float* __restrict__ b1,      // [HID]
    const int* __restrict__ map1)      // [N1] int32
{
    __shared__ uint32_t Ah[2][128 * APITCH];
    __shared__ uint32_t Al[2][128 * APITCH];
    __shared__ uint32_t Bh[2][128 * APITCH];
    __shared__ uint32_t Bl[2][128 * APITCH];

    const int tid  = threadIdx.x;
    const int warp = tid >> 5;
    const int lane = tid & 31;
    const int g    = lane >> 2;
    const int i4   = lane & 3;

    const int row0 = blockIdx.x * 128;

    const int lr = tid >> 1;
    const int kh = (tid & 1) * 8;
    const int sidx = lr * APITCH + (kh >> 1);

    const int  grow   = row0 + lr;
    const bool rvalid = (grow < N1);
    const int  src    = rvalid ? map1[grow] : 0;
    const float* arow = features + (size_t)src * INF;
    const float* wrow = W1 + (size_t)lr * INF;

    float acc[16][4];
    #pragma unroll
    for (int t = 0; t < 16; t++)
        #pragma unroll
        for (int j = 0; j < 4; j++) acc[t][j] = 0.f;

    float sa[8], sb[8];

    auto load_regs = [&](int k0) {
        #pragma unroll
        for (int j = 0; j < 8; j += 2) {
            const int k = k0 + kh + j;      // always even -> 8B aligned
            if (k + 1 < INF) {
                if (rvalid) {
                    float2 v = *(const float2*)(arow + k);
                    sa[j] = v.x; sa[j+1] = v.y;
                } else {
                    sa[j] = 0.f; sa[j+1] = 0.f;
                }
                float2 w = *(const float2*)(wrow + k);
                sb[j] = w.x; sb[j+1] = w.y;
            } else {
                sa[j]   = (rvalid && k     < INF) ? arow[k]     : 0.f;
                sa[j+1] = (rvalid && k + 1 < INF) ? arow[k + 1] : 0.f;
                sb[j]   = (k     < INF) ? wrow[k]     : 0.f;
                sb[j+1] = (k + 1 < INF) ? wrow[k + 1] : 0.f;
            }
        }
    };

    auto store_stage = [&](int b) {
        #pragma unroll
        for (int j = 0; j < 4; j++) {
            split_pair(sa[2*j], sa[2*j+1], Ah[b][sidx + j], Al[b][sidx + j]);
            split_pair(sb[2*j], sb[2*j+1], Bh[b][sidx + j], Bl[b][sidx + j]);
        }
    };

    load_regs(0);
    store_stage(0);
    __syncthreads();

    const int ra = (warp * 16 + g) * APITCH;

    #pragma unroll 1
    for (int s = 0; s < KSTEPS; s++) {
        if (s + 1 < KSTEPS) load_regs((s + 1) * 16);

        const int b = s & 1;
        uint32_t ah0 = Ah[b][ra + i4];
        uint32_t ah1 = Ah[b][ra + 8 * APITCH + i4];
        uint32_t ah2 = Ah[b][ra + i4 + 4];
        uint32_t ah3 = Ah[b][ra + 8 * APITCH + i4 + 4];
        uint32_t al0 = Al[b][ra + i4];
        uint32_t al1 = Al[b][ra + 8 * APITCH + i4];
        uint32_t al2 = Al[b][ra + i4 + 4];
        uint32_t al3 = Al[b][ra + 8 * APITCH + i4 + 4];

        #pragma unroll
        for (int nt = 0; nt < 16; nt++) {
            const int rb = (nt * 8 + g) * APITCH;
            uint32_t b0h = Bh[b][rb + i4];
            uint32_t b1h = Bh[b][rb + i4 + 4];
            uint32_t b0l = Bl[b][rb + i4];
            uint32_t b1l = Bl[b][rb + i4 + 4];
            mma_bf16(acc[nt], ah0, ah1, ah2, ah3, b0h, b1h);
            mma_bf16(acc[nt], ah0, ah1, ah2, ah3, b0l, b1l);
            mma_bf16(acc[nt], al0, al1, al2, al3, b0h, b1h);
        }

        if (s + 1 < KSTEPS) store_stage((s + 1) & 1);
        __syncthreads();
    }

    const int r0g = row0 + warp * 16 + g;
    const int r1g = r0g + 8;
    #pragma unroll
    for (int nt = 0; nt < 16; nt++) {
        const int col = nt * 8 + 2 * i4;
        const float bb0 = b1[col], bb1 = b1[col + 1];
        if (r0g < N1) {
            float v0 = acc[nt][0] + bb0, v1 = acc[nt][1] + bb1;
            float2 o = make_float2(v0 > 0.f ? v0 : 0.f, v1 > 0.f ? v1 : 0.f);
            *(float2*)(&g_H1[(size_t)r0g * HID + col]) = o;
        }
        if (r1g < N1) {
            float v0 = acc[nt][2] + bb0, v1 = acc[nt][3] + bb1;
            float2 o = make_float2(v0 > 0.f ? v0 : 0.f, v1 > 0.f ? v1 : 0.f);
            *(float2*)(&g_H1[(size_t)r1g * HID + col]) = o;
        }
    }
}

// ---------------------------------------------------------------------------
// Kernel 2 (NEW): G[N1,44] = H1[N1,128] @ W2^T, tensor cores, bf16 hi/lo.
// Block: 256 thr / 8 warps, 128 rows per block, 8 k16 chunks, 6 n8 tiles.
// smem ~16.5 KB -> high occupancy; same pitch-12 conflict-free layout as k1.
// ---------------------------------------------------------------------------
#define NROWS_B 48    // padded class rows (6 * n8)
__global__ __launch_bounds__(256) void k_logits(
    const float* __restrict__ W2)          // [CLS][HID]
{
    __shared__ uint32_t Ah[128 * APITCH];
    __shared__ uint32_t Al[128 * APITCH];
    __shared__ uint32_t Bh[NROWS_B * APITCH];
    __shared__ uint32_t Bl[NROWS_B * APITCH];

    const int tid  = threadIdx.x;
    const int warp = tid >> 5;
    const int lane = tid & 31;
    const int g    = lane >> 2;
    const int i4   = lane & 3;

    const int row0 = blockIdx.x * 128;

    // A staging: 2 threads per row (256 = 128*2)
    const int lr = tid >> 1;
    const int kh = (tid & 1) * 8;
    const int asidx = lr * APITCH + (kh >> 1);
    const int  grow   = row0 + lr;
    const bool avalid = (grow < N1);

    // B staging: tid < 96 covers 48 rows * 2
    const int  wr     = tid >> 1;            // same as lr; valid when tid<96
    const bool bstage = (tid < 96);
    const bool bvalid = bstage && (wr < CLS);

    float acc[6][4];
    #pragma unroll
    for (int t = 0; t < 6; t++)
        #pragma unroll
        for (int j = 0; j < 4; j++) acc[t][j] = 0.f;

    const int ra = (warp * 16 + g) * APITCH;

    #pragma unroll 1
    for (int kc = 0; kc < 8; kc++) {
        const int k0 = kc * 16 + kh;

        // load A: g_H1 rows 512B-aligned, k0 multiple of 8 -> float4 legal
        float va[8];
        if (avalid) {
            float4 v0 = *(const float4*)(&g_H1[(size_t)grow * HID + k0]);
            float4 v1 = *(const float4*)(&g_H1[(size_t)grow * HID + k0 + 4]);
            va[0]=v0.x; va[1]=v0.y; va[2]=v0.z; va[3]=v0.w;
            va[4]=v1.x; va[5]=v1.y; va[6]=v1.z; va[7]=v1.w;
        } else {
            #pragma unroll
            for (int j = 0; j < 8; j++) va[j] = 0.f;
        }
        // load B: W2 rows 512B-aligned
        float vb[8];
        if (bvalid) {
            float4 w0 = *(const float4*)(&W2[(size_t)wr * HID + k0]);
            float4 w1 = *(const float4*)(&W2[(size_t)wr * HID + k0 + 4]);
            vb[0]=w0.x; vb[1]=w0.y; vb[2]=w0.z; vb[3]=w0.w;
            vb[4]=w1.x; vb[5]=w1.y; vb[6]=w1.z; vb[7]=w1.w;
        } else {
            #pragma unroll
            for (int j = 0; j < 8; j++) vb[j] = 0.f;
        }

        __syncthreads();   // previous chunk's MMA reads done
        #pragma unroll
        for (int j = 0; j < 4; j++)
            split_pair(va[2*j], va[2*j+1], Ah[asidx + j], Al[asidx + j]);
        if (bstage) {
            #pragma unroll
            for (int j = 0; j < 4; j++)
                split_pair(vb[2*j], vb[2*j+1], Bh[asidx + j], Bl[asidx + j]);
        }
        __syncthreads();

        uint32_t ah0 = Ah[ra + i4];
        uint32_t ah1 = Ah[ra + 8 * APITCH + i4];
        uint32_t ah2 = Ah[ra + i4 + 4];
        uint32_t ah3 = Ah[ra + 8 * APITCH + i4 + 4];
        uint32_t al0 = Al[ra + i4];
        uint32_t al1 = Al[ra + 8 * APITCH + i4];
        uint32_t al2 = Al[ra + i4 + 4];
        uint32_t al3 = Al[ra + 8 * APITCH + i4 + 4];

        #pragma unroll
        for (int nt = 0; nt < 6; nt++) {
            const int rb = (nt * 8 + g) * APITCH;
            uint32_t b0h = Bh[rb + i4];
            uint32_t b1h = Bh[rb + i4 + 4];
            uint32_t b0l = Bl[rb + i4];
            uint32_t b1l = Bl[rb + i4 + 4];
            mma_bf16(acc[nt], ah0, ah1, ah2, ah3, b0h, b1h);
            mma_bf16(acc[nt], ah0, ah1, ah2, ah3, b0l, b1l);
            mma_bf16(acc[nt], al0, al1, al2, al3, b0h, b1h);
        }
    }

    // epilogue -> g_G (cols >= CLSP dropped; cols 41..43 never read by gather)
    const int r0g = row0 + warp * 16 + g;
    const int r1g = r0g + 8;
    #pragma unroll
    for (int nt = 0; nt < 6; nt++) {
        const int col = nt * 8 + 2 * i4;
        if (col + 1 < CLSP) {
            if (r0g < N1)
                *(float2*)(&g_G[(size_t)r0g * CLSP + col]) =
                    make_float2(acc[nt][0], acc[nt][1]);
            if (r1g < N1)
                *(float2*)(&g_G[(size_t)r1g * CLSP + col]) =
                    make_float2(acc[nt][2], acc[nt][3]);
        }
    }
}

// ---------------------------------------------------------------------------
// Kernel 3: out[n][c] = b2[c] + mean_j G[neigh[n][j]][c]
// 4 seeds per block of 256 (64-lane groups, 41 active lanes).
// ---------------------------------------------------------------------------
__global__ __launch_bounds__(256) void k_gather(
    const int* __restrict__ neigh,         // [N2][FAN] int32
    const float* __restrict__ b2,          // [CLS]
    float* __restrict__ out)               // [N2][CLS]
{
    const int tid  = threadIdx.x;
    const int grp  = tid >> 6;
    const int lane = tid & 63;
    const int n    = blockIdx.x * 4 + grp;
    if (n >= N2C || lane >= CLS) return;

    const int* nb = neigh + (size_t)n * FAN;
    float s = 0.f;
    #pragma unroll
    for (int j = 0; j < FAN; j++) {
        int idx = nb[j];
        s += g_G[(size_t)idx * CLSP + lane];
    }
    out[(size_t)n * CLS + lane] = fmaf(s, 1.0f / FAN, b2[lane]);
}

// ---------------------------------------------------------------------------
// Launch.  Inputs: features f32, W1 f32, b1 f32, W2 f32, b2 f32,
//                  map1 i32, neigh_idx i32.  Output: f32 [N2*CLS].
// ---------------------------------------------------------------------------
extern "C" void kernel_launch(void* const* d_in, const int* in_sizes, int n_in,
                              void* d_out, int out_size) {
    const float* features = (const float*)d_in[0];
    const float* W1       = (const float*)d_in[1];
    const float* b1       = (const float*)d_in[2];
    const float* W2       = (const float*)d_in[3];
    const float* b2       = (const float*)d_in[4];
    const int*   map1     = (const int*)d_in[5];
    const int*   neigh    = (const int*)d_in[6];
    float*       out      = (float*)d_out;

    const int grid1 = (N1 + 127) / 128;        // 391
    k_layer1<<<grid1, 256>>>(features, W1, b1, map1);

    const int grid2 = (N1 + 127) / 128;        // 391
    k_logits<<<grid2, 256>>>(W2);

    const int grid3 = (N2C + 3) / 4;           // 2500
    k_gather<<<grid3, 256>>>(neigh, b2, out);
}

// round 8
// speedup vs baseline: 3.0552x; 1.0503x over previous
#include <cuda_runtime.h>
#include <cuda_bf16.h>
#include <cstdint>

// Problem constants
#define N0    200000
#define N1    50000
#define N2C   10000
#define INF   602
#define HID   128
#define CLS   41
#define CLSP  44
#define FAN   25

#define KSTEPS 38     // 38*16 = 608 >= 602
#define APITCH 12     // u32 pitch per row -> conflict-free fragment reads
#define KPAIRS 304    // 608/2 bf16-pairs per W1 row (padded)

// Device scratch
__device__ float    g_H1[N1 * HID];
__device__ float    g_G [N1 * CLSP];
__device__ uint32_t g_W1h[HID * KPAIRS];   // W1 as bf16x2 hi
__device__ uint32_t g_W1l[HID * KPAIRS];   // W1 as bf16x2 lo

// ---- dynamic smem layout for k_layer1 (byte offsets) ----
#define AF32_STAGE 12288                  // 128 rows * 12 float2 (96B/row)
#define AF32_OFF   0                      // 3 stages
#define BSTAGE     6144                   // 128 rows * 12 u32 (48B/row)
#define BH_OFF     (AF32_OFF + 3 * AF32_STAGE)   // 36864
#define BL_OFF     (BH_OFF + 3 * BSTAGE)         // 55296
#define ABH_OFF    (BL_OFF + 3 * BSTAGE)         // 73728
#define ABL_OFF    (ABH_OFF + 6144)              // 79872
#define SMEM_L1    (ABL_OFF + 6144)              // 86016 bytes

// ---------------------------------------------------------------------------
// helpers
// ---------------------------------------------------------------------------
__device__ __forceinline__ void mma_bf16(float c[4],
                                         uint32_t a0, uint32_t a1, uint32_t a2, uint32_t a3,
                                         uint32_t b0, uint32_t b1)
{
    asm volatile(
        "mma.sync.aligned.m16n8k16.row.col.f32.bf16.bf16.f32 "
        "{%0,%1,%2,%3}, {%4,%5,%6,%7}, {%8,%9}, {%0,%1,%2,%3};\n"
        : "+f"(c[0]), "+f"(c[1]), "+f"(c[2]), "+f"(c[3])
        : "r"(a0), "r"(a1), "r"(a2), "r"(a3), "r"(b0), "r"(b1));
}

__device__ __forceinline__ void split_pair(float x0, float x1,
                                           uint32_t& hi, uint32_t& lo)
{
    __nv_bfloat162 h2 = __floats2bfloat162_rn(x0, x1);
    float2 hf = __bfloat1622float2(h2);
    __nv_bfloat162 l2 = __floats2bfloat162_rn(x0 - hf.x, x1 - hf.y);
    hi = *reinterpret_cast<uint32_t*>(&h2);
    lo = *reinterpret_cast<uint32_t*>(&l2);
}

__device__ __forceinline__ void cp8(uint32_t dst, const void* src, int sz) {
    asm volatile("cp.async.ca.shared.global [%0], [%1], 8, %2;\n"
                 :: "r"(dst), "l"(src), "r"(sz));
}
__device__ __forceinline__ void cp16(uint32_t dst, const void* src) {
    asm volatile("cp.async.cg.shared.global [%0], [%1], 16;\n"
                 :: "r"(dst), "l"(src));
}
#define CP_COMMIT() asm volatile("cp.async.commit_group;\n" ::: "memory")
#define CP_WAIT(n)  asm volatile("cp.async.wait_group %0;\n" :: "n"(n) : "memory")

// ---------------------------------------------------------------------------
// Kernel 0: pre-convert W1 -> bf16 hi/lo, k padded to 608
// ---------------------------------------------------------------------------
__global__ __launch_bounds__(256) void k_prep(const float* __restrict__ W1)
{
    int idx = blockIdx.x * 256 + threadIdx.x;
    if (idx >= HID * KPAIRS) return;
    int row = idx / KPAIRS;
    int p   = idx % KPAIRS;
    int k   = 2 * p;
    float x0 = (k     < INF) ? W1[(size_t)row * INF + k]     : 0.f;
    float x1 = (k + 1 < INF) ? W1[(size_t)row * INF + k + 1] : 0.f;
    uint32_t h, l;
    split_pair(x0, x1, h, l);
    g_W1h[idx] = h;
    g_W1l[idx] = l;
}

// ---------------------------------------------------------------------------
// Kernel 1: H1[r] = relu( features[map1[r]] @ W1^T + b1 )
// cp.async 3-deep pipeline (A fp32 ring + pre-converted B bf16 ring),
// per-stage A convert, bf16 hi/lo 3-term MMA (same fragment math as R6).
// ---------------------------------------------------------------------------
__global__ __launch_bounds__(256, 2) void k_layer1(
    const float* __restrict__ features,
    const float* __restrict__ b1,
    const int* __restrict__ map1)
{
    extern __shared__ char smem[];
    const uint32_t sbase = (uint32_t)__cvta_generic_to_shared(smem);

    const int tid  = threadIdx.x;
    const int warp = tid >> 5;
    const int lane = tid & 31;
    const int g    = lane >> 2;
    const int i4   = lane & 3;
    const int row0 = blockIdx.x * 128;

    // staging role: 2 threads per row, 8 k-floats each
    const int lr   = tid >> 1;
    const int kh   = (tid & 1) * 8;
    const int half = tid & 1;
    const int sp   = lr * APITCH + (kh >> 1);   // slot base (u32 / float2 units)

    const int  grow   = row0 + lr;
    const bool rvalid = (grow < N1);
    const int  src    = rvalid ? map1[grow] : 0;
    const float* arow = features + (size_t)src * INF;

    // smem views
    uint32_t* abh = (uint32_t*)(smem + ABH_OFF);
    uint32_t* abl = (uint32_t*)(smem + ABL_OFF);

    float acc[16][4];
    #pragma unroll
    for (int t = 0; t < 16; t++)
        #pragma unroll
        for (int j = 0; j < 4; j++) acc[t][j] = 0.f;

    // ---- async stage issue: A fp32 (4x 8B) + B hi/lo (1x 16B each) ----
    auto issue = [&](int p) {
        const int slot = p % 3;
        const uint32_t adst = sbase + AF32_OFF + slot * AF32_STAGE + sp * 8;
        #pragma unroll
        for (int j = 0; j < 4; j++) {
            const int kg = p * 16 + kh + 2 * j;
            const int sz = (rvalid && kg < INF) ? 8 : 0;
            const float* s = arow + (kg < INF ? kg : 0);   // clamp (unread if sz=0)
            cp8(adst + j * 8, s, sz);
        }
        const uint32_t boff = slot * BSTAGE + lr * 48 + half * 16;
        const uint32_t gidx = (uint32_t)lr * KPAIRS + p * 8 + half * 4;
        cp16(sbase + BH_OFF + boff, g_W1h + gidx);
        cp16(sbase + BL_OFF + boff, g_W1l + gidx);
        CP_COMMIT();
    };

    issue(0);
    issue(1);

    const int ra = (warp * 16 + g) * APITCH;

    #pragma unroll 1
    for (int s = 0; s < KSTEPS; s++) {
        if (s == KSTEPS - 1) { CP_WAIT(0); } else { CP_WAIT(1); }
        __syncthreads();                 // stage s visible; MMA(s-1) complete

        if (s + 2 < KSTEPS) issue(s + 2);   // writes slot (s-1)%3 (now free)

        const int slot = s % 3;

        // convert A stage s: fp32 smem -> bf16 hi/lo smem (4 pairs/thread)
        {
            const float2* af = (const float2*)(smem + AF32_OFF + slot * AF32_STAGE);
            #pragma unroll
            for (int j = 0; j < 4; j++) {
                float2 v = af[sp + j];
                split_pair(v.x, v.y, abh[sp + j], abl[sp + j]);
            }
        }
        __syncthreads();                 // A bf16 tile ready

        // MMA on stage s (identical fragment math to R6)
        const uint32_t* bh = (const uint32_t*)(smem + BH_OFF + slot * BSTAGE);
        const uint32_t* bl = (const uint32_t*)(smem + BL_OFF + slot * BSTAGE);

        uint32_t ah0 = abh[ra + i4];
        uint32_t ah1 = abh[ra + 8 * APITCH + i4];
        uint32_t ah2 = abh[ra + i4 + 4];
        uint32_t ah3 = abh[ra + 8 * APITCH + i4 + 4];
        uint32_t al0 = abl[ra + i4];
        uint32_t al1 = abl[ra + 8 * APITCH + i4];
        uint32_t al2 = abl[ra + i4 + 4];
        uint32_t al3 = abl[ra + 8 * APITCH + i4 + 4];

        #pragma unroll
        for (int nt = 0; nt < 16; nt++) {
            const int rb = (nt * 8 + g) * APITCH;
            uint32_t b0h = bh[rb + i4];
            uint32_t b1h = bh[rb + i4 + 4];
            uint32_t b0l = bl[rb + i4];
            uint32_t b1l = bl[rb + i4 + 4];
            mma_bf16(acc[nt], ah0, ah1, ah2, ah3, b0h, b1h);
            mma_bf16(acc[nt], ah0, ah1, ah2, ah3, b0l, b1l);
            mma_bf16(acc[nt], al0, al1, al2, al3, b0h, b1h);
        }
    }

    // ---- epilogue: bias + relu -> g_H1 ----
    const int r0g = row0 + warp * 16 + g;
    const int r1g = r0g + 8;
    #pragma unroll
    for (int nt = 0; nt < 16; nt++) {
        const int col = nt * 8 + 2 * i4;
        const float bb0 = b1[col], bb1 = b1[col + 1];
        if (r0g < N1) {
            float v0 = acc[nt][0] + bb0, v1 = acc[nt][1] + bb1;
            *(float2*)(&g_H1[(size_t)r0g * HID + col]) =
                make_float2(v0 > 0.f ? v0 : 0.f, v1 > 0.f ? v1 : 0.f);
        }
        if (r1g < N1) {
            float v0 = acc[nt][2] + bb0, v1 = acc[nt][3] + bb1;
            *(float2*)(&g_H1[(size_t)r1g * HID + col]) =
                make_float2(v0 > 0.f ? v0 : 0.f, v1 > 0.f ? v1 : 0.f);
        }
    }
}

// ---------------------------------------------------------------------------
// Kernel 2: G[N1,44] = H1[N1,128] @ W2^T, tensor cores, bf16 hi/lo (R7, good)
// ---------------------------------------------------------------------------
#define NROWS_B 48
__global__ __launch_bounds__(256) void k_logits(
    const float* __restrict__ W2)
{
    __shared__ uint32_t Ah[128 * APITCH];
    __shared__ uint32_t Al[128 * APITCH];
    __shared__ uint32_t Bh[NROWS_B * APITCH];
    __shared__ uint32_t Bl[NROWS_B * APITCH];

    const int tid  = threadIdx.x;
    const int warp = tid >> 5;
    const int lane = tid & 31;
    const int g    = lane >> 2;
    const int i4   = lane & 3;
    const int row0 = blockIdx.x * 128;

    const int lr = tid >> 1;
    const int kh = (tid & 1) * 8;
    const int asidx = lr * APITCH + (kh >> 1);
    const int  grow   = row0 + lr;
    const bool avalid = (grow < N1);

    const int  wr     = tid >> 1;
    const bool bstage = (tid < 96);
    const bool bvalid = bstage && (wr < CLS);

    float acc[6][4];
    #pragma unroll
    for (int t = 0; t < 6; t++)
        #pragma unroll
        for (int j = 0; j < 4; j++) acc[t][j] = 0.f;

    const int ra = (warp * 16 + g) * APITCH;

    #pragma unroll 1
    for (int kc = 0; kc < 8; kc++) {
        const int k0 = kc * 16 + kh;

        float va[8];
        if (avalid) {
            float4 v0 = *(const float4*)(&g_H1[(size_t)grow * HID + k0]);
            float4 v1 = *(const float4*)(&g_H1[(size_t)grow * HID + k0 + 4]);
            va[0]=v0.x; va[1]=v0.y; va[2]=v0.z; va[3]=v0.w;
            va[4]=v1.x; va[5]=v1.y; va[6]=v1.z; va[7]=v1.w;
        } else {
            #pragma unroll
            for (int j = 0; j < 8; j++) va[j] = 0.f;
        }
        float vb[8];
        if (bvalid) {
            float4 w0 = *(const float4*)(&W2[(size_t)wr * HID + k0]);
            float4 w1 = *(const float4*)(&W2[(size_t)wr * HID + k0 + 4]);
            vb[0]=w0.x; vb[1]=w0.y; vb[2]=w0.z; vb[3]=w0.w;
            vb[4]=w1.x; vb[5]=w1.y; vb[6]=w1.z; vb[7]=w1.w;
        } else {
            #pragma unroll
            for (int j = 0; j < 8; j++) vb[j] = 0.f;
        }

        __syncthreads();
        #pragma unroll
        for (int j = 0; j < 4; j++)
            split_pair(va[2*j], va[2*j+1], Ah[asidx + j], Al[asidx + j]);
        if (bstage) {
            #pragma unroll
            for (int j = 0; j < 4; j++)
                split_pair(vb[2*j], vb[2*j+1], Bh[asidx + j], Bl[asidx + j]);
        }
        __syncthreads();

        uint32_t ah0 = Ah[ra + i4];
        uint32_t ah1 = Ah[ra + 8 * APITCH + i4];
        uint32_t ah2 = Ah[ra + i4 + 4];
        uint32_t ah3 = Ah[ra + 8 * APITCH + i4 + 4];
        uint32_t al0 = Al[ra + i4];
        uint32_t al1 = Al[ra + 8 * APITCH + i4];
        uint32_t al2 = Al[ra + i4 + 4];
        uint32_t al3 = Al[ra + 8 * APITCH + i4 + 4];

        #pragma unroll
        for (int nt = 0; nt < 6; nt++) {
            const int rb = (nt * 8 + g) * APITCH;
            uint32_t b0h = Bh[rb + i4];
            uint32_t b1h = Bh[rb + i4 + 4];
            uint32_t b0l = Bl[rb + i4];
            uint32_t b1l = Bl[rb + i4 + 4];
            mma_bf16(acc[nt], ah0, ah1, ah2, ah3, b0h, b1h);
            mma_bf16(acc[nt], ah0, ah1, ah2, ah3, b0l, b1l);
            mma_bf16(acc[nt], al0, al1, al2, al3, b0h, b1h);
        }
    }

    const int r0g = row0 + warp * 16 + g;
    const int r1g = r0g + 8;
    #pragma unroll
    for (int nt = 0; nt < 6; nt++) {
        const int col = nt * 8 + 2 * i4;
        if (col + 1 < CLSP) {
            if (r0g < N1)
                *(float2*)(&g_G[(size_t)r0g * CLSP + col]) =
                    make_float2(acc[nt][0], acc[nt][1]);
            if (r1g < N1)
                *(float2*)(&g_G[(size_t)r1g * CLSP + col]) =
                    make_float2(acc[nt][2], acc[nt][3]);
        }
    }
}

// ---------------------------------------------------------------------------
// Kernel 3: out[n][c] = b2[c] + mean_j G[neigh[n][j]][c]
// ---------------------------------------------------------------------------
__global__ __launch_bounds__(256) void k_gather(
    const int* __restrict__ neigh,
    const float* __restrict__ b2,
    float* __restrict__ out)
{
    const int tid  = threadIdx.x;
    const int grp  = tid >> 6;
    const int lane = tid & 63;
    const int n    = blockIdx.x * 4 + grp;
    if (n >= N2C || lane >= CLS) return;

    const int* nb = neigh + (size_t)n * FAN;
    float s = 0.f;
    #pragma unroll
    for (int j = 0; j < FAN; j++) {
        int idx = nb[j];
        s += g_G[(size_t)idx * CLSP + lane];
    }
    out[(size_t)n * CLS + lane] = fmaf(s, 1.0f / FAN, b2[lane]);
}

// ---------------------------------------------------------------------------
// Launch.  Inputs: features f32, W1 f32, b1 f32, W2 f32, b2 f32,
//                  map1 i32, neigh_idx i32.  Output: f32 [N2*CLS].
// ---------------------------------------------------------------------------
extern "C" void kernel_launch(void* const* d_in, const int* in_sizes, int n_in,
                              void* d_out, int out_size) {
    const float* features = (const float*)d_in[0];
    const float* W1       = (const float*)d_in[1];
    const float* b1       = (const float*)d_in[2];
    const float* W2       = (const float*)d_in[3];
    const float* b2       = (const float*)d_in[4];
    const int*   map1     = (const int*)d_in[5];
    const int*   neigh    = (const int*)d_in[6];
    float*       out      = (float*)d_out;

    static bool attr_done = false;
    if (!attr_done) {
        cudaFuncSetAttribute(k_layer1,
                             cudaFuncAttributeMaxDynamicSharedMemorySize, SMEM_L1);
        attr_done = true;
    }

    const int gridp = (HID * KPAIRS + 255) / 256;   // 152
    k_prep<<<gridp, 256>>>(W1);

    const int grid1 = (N1 + 127) / 128;             // 391
    k_layer1<<<grid1, 256, SMEM_L1>>>(features, b1, map1);

    k_logits<<<grid1, 256>>>(W2);

    const int grid3 = (N2C + 3) / 4;                // 2500
    k_gather<<<grid3, 256>>>(neigh, b2, out);
}

// round 9
// speedup vs baseline: 4.0208x; 1.3160x over previous
#include <cuda_runtime.h>
#include <cuda_bf16.h>
#include <cstdint>

// Problem constants
#define N0    200000
#define N1    50000
#define N2C   10000
#define INF   602
#define HID   128
#define CLS   41
#define CLSP  44
#define FAN   25

#define KSTEPS 38     // 38*16 = 608 >= 602
#define APITCH 12     // (k_logits only) u32 pitch -> conflict-free frags
#define AP     14     // k_layer1 A-conv smem pitch (u32 per row)

// Device scratch
__device__ float    g_H1[N1 * HID];
__device__ float    g_G [N1 * CLSP];
// W1 pre-converted, k-chunk-major, MMA-pair-permuted: [38][128][8] u32
__device__ __align__(16) uint32_t g_W1kh[KSTEPS * HID * 8];
__device__ __align__(16) uint32_t g_W1kl[KSTEPS * HID * 8];

// ---- dynamic smem layout for k_layer1 (byte offsets) ----
#define AH_OFF   0                         // 2 bufs x 128*AP u32 = 14336 B
#define AL_OFF   14336
#define BH_OFF   28672                     // 3 slots x 4096 B
#define BL_OFF   40960
#define SMEM_L1  53248

// ---------------------------------------------------------------------------
// helpers
// ---------------------------------------------------------------------------
__device__ __forceinline__ void mma_bf16(float c[4],
                                         uint32_t a0, uint32_t a1, uint32_t a2, uint32_t a3,
                                         uint32_t b0, uint32_t b1)
{
    asm volatile(
        "mma.sync.aligned.m16n8k16.row.col.f32.bf16.bf16.f32 "
        "{%0,%1,%2,%3}, {%4,%5,%6,%7}, {%8,%9}, {%0,%1,%2,%3};\n"
        : "+f"(c[0]), "+f"(c[1]), "+f"(c[2]), "+f"(c[3])
        : "r"(a0), "r"(a1), "r"(a2), "r"(a3), "r"(b0), "r"(b1));
}

__device__ __forceinline__ void split_pair(float x0, float x1,
                                           uint32_t& hi, uint32_t& lo)
{
    __nv_bfloat162 h2 = __floats2bfloat162_rn(x0, x1);
    float2 hf = __bfloat1622float2(h2);
    __nv_bfloat162 l2 = __floats2bfloat162_rn(x0 - hf.x, x1 - hf.y);
    hi = *reinterpret_cast<uint32_t*>(&h2);
    lo = *reinterpret_cast<uint32_t*>(&l2);
}

__device__ __forceinline__ void cp16(uint32_t dst, const void* src) {
    asm volatile("cp.async.cg.shared.global [%0], [%1], 16;\n"
                 :: "r"(dst), "l"(src));
}
#define CP_COMMIT() asm volatile("cp.async.commit_group;\n" ::: "memory")
#define CP_WAIT(n)  asm volatile("cp.async.wait_group %0;\n" :: "n"(n) : "memory")

// ---------------------------------------------------------------------------
// Kernel 0: W1 -> bf16 hi/lo, k-chunk-major slabs with MMA-pair permutation.
// slab[p][r][c]: c = (i<4) ? 2i : 2(i-4)+1  for original pair i (k = 16p+2i)
// ---------------------------------------------------------------------------
__global__ __launch_bounds__(256) void k_prep(const float* __restrict__ W1)
{
    int idx = blockIdx.x * 256 + threadIdx.x;
    if (idx >= KSTEPS * HID * 8) return;
    const int p   = idx >> 10;           // /1024
    const int rem = idx & 1023;
    const int r   = rem >> 3;
    const int i   = rem & 7;
    const int c   = (i < 4) ? (2 * i) : (2 * (i - 4) + 1);
    const int k0  = p * 16 + 2 * i;
    float x0 = (k0     < INF) ? W1[(size_t)r * INF + k0]     : 0.f;
    float x1 = (k0 + 1 < INF) ? W1[(size_t)r * INF + k0 + 1] : 0.f;
    uint32_t h, l;
    split_pair(x0, x1, h, l);
    const int didx = (p * HID + r) * 8 + c;
    g_W1kh[didx] = h;
    g_W1kl[didx] = l;
}

// ---------------------------------------------------------------------------
// Kernel 1: H1[r] = relu( features[map1[r]] @ W1^T + b1 )
// bf16 hi/lo 3-term MMA. BM=128, BN=128, 8 warps (warp tile 32x64).
// A: coalesced-by-row LDG.64 (8 lanes x same row) + reg prefetch, STS convert.
// B: contiguous 4KB k-slab cp.async ring (3-deep). One barrier per stage.
// ---------------------------------------------------------------------------
__global__ __launch_bounds__(256, 2) void k_layer1(
    const float* __restrict__ features,
    const float* __restrict__ b1,
    const int* __restrict__ map1)
{
    extern __shared__ char smem[];
    const uint32_t sbase = (uint32_t)__cvta_generic_to_shared(smem);
    uint32_t* AHs = (uint32_t*)(smem + AH_OFF);          // [2][128*AP]
    uint32_t* ALs = (uint32_t*)(smem + AL_OFF);
    const uint32_t* BHs = (const uint32_t*)(smem + BH_OFF); // [3][1024]
    const uint32_t* BLs = (const uint32_t*)(smem + BL_OFF);

    const int tid  = threadIdx.x;
    const int warp = tid >> 5;
    const int lane = tid & 31;
    const int g    = lane >> 2;        // 0..7
    const int i4   = lane & 3;         // 0..3
    const int q    = lane >> 3;        // 0..3  (staging row group)
    const int o    = lane & 7;         // 0..7  (staging pair within 64B chunk)
    const int co   = (o < 4) ? (2 * o) : (2 * (o - 4) + 1);  // permuted col

    const int row0 = blockIdx.x * 128;

    // 4 staged rows per thread: R_j = warp*16 + 4j + q
    const float* aptr[4];
    bool rv[4];
    int  Rl[4];
    #pragma unroll
    for (int j = 0; j < 4; j++) {
        const int R  = warp * 16 + 4 * j + q;
        const int gr = row0 + R;
        Rl[j] = R;
        rv[j] = (gr < N1);
        const int src = rv[j] ? map1[gr] : 0;
        aptr[j] = features + (size_t)src * INF + 2 * o;   // element offset baked
    }

    float2 cur[4];
    auto ldA = [&](int p) {
        const bool kv = (16 * p + 2 * o + 1) < INF;   // only stage 37 can fail
        #pragma unroll
        for (int j = 0; j < 4; j++) {
            cur[j] = (rv[j] && kv) ? *(const float2*)(aptr[j] + 16 * p)
                                   : make_float2(0.f, 0.f);
        }
    };

    auto issueB = [&](int p) {
        const int slot = p % 3;
        cp16(sbase + BH_OFF + slot * 4096 + tid * 16, g_W1kh + p * 1024 + tid * 4);
        cp16(sbase + BL_OFF + slot * 4096 + tid * 16, g_W1kl + p * 1024 + tid * 4);
        CP_COMMIT();
    };

    ldA(0);
    issueB(0);
    issueB(1);

    float acc[2][8][4];
    #pragma unroll
    for (int mg = 0; mg < 2; mg++)
        #pragma unroll
        for (int nt = 0; nt < 8; nt++)
            #pragma unroll
            for (int j = 0; j < 4; j++) acc[mg][nt][j] = 0.f;

    const int rowblk = (warp & 3) * 32;
    const int colblk = (warp >> 2) * 64;

    #pragma unroll 1
    for (int s = 0; s < KSTEPS; s++) {
        // convert + store stage s
        uint32_t* ah = AHs + (s & 1) * (128 * AP);
        uint32_t* al = ALs + (s & 1) * (128 * AP);
        #pragma unroll
        for (int j = 0; j < 4; j++) {
            uint32_t h, l;
            split_pair(cur[j].x, cur[j].y, h, l);
            ah[Rl[j] * AP + co] = h;
            al[Rl[j] * AP + co] = l;
        }
        if (s + 1 < KSTEPS) ldA(s + 1);       // prefetch next stage A

        CP_WAIT(1);                           // B slab s arrived (this thread)
        __syncthreads();                      // A tile + B slab visible; prior MMA done
        if (s + 2 < KSTEPS) issueB(s + 2);

        const uint32_t* bh = BHs + (s % 3) * 1024;
        const uint32_t* bl = BLs + (s % 3) * 1024;

        // A fragments (LDS.64 pairs; permuted layout => (a0,a2)/(a1,a3) adjacent)
        uint32_t ah0[2], ah1[2], ah2[2], ah3[2];
        uint32_t al0[2], al1[2], al2[2], al3[2];
        #pragma unroll
        for (int mg = 0; mg < 2; mg++) {
            const int r = rowblk + mg * 16 + g;
            uint2 h0 = *(const uint2*)&ah[r * AP + 2 * i4];
            uint2 h1 = *(const uint2*)&ah[(r + 8) * AP + 2 * i4];
            uint2 l0 = *(const uint2*)&al[r * AP + 2 * i4];
            uint2 l1 = *(const uint2*)&al[(r + 8) * AP + 2 * i4];
            ah0[mg] = h0.x; ah2[mg] = h0.y; ah1[mg] = h1.x; ah3[mg] = h1.y;
            al0[mg] = l0.x; al2[mg] = l0.y; al1[mg] = l1.x; al3[mg] = l1.y;
        }

        #pragma unroll
        for (int nt = 0; nt < 8; nt++) {
            const int rb = (colblk + nt * 8 + g) * 8 + 2 * i4;
            uint2 bhp = *(const uint2*)&bh[rb];   // (b0h, b1h)
            uint2 blp = *(const uint2*)&bl[rb];   // (b0l, b1l)
            #pragma unroll
            for (int mg = 0; mg < 2; mg++) {
                mma_bf16(acc[mg][nt], ah0[mg], ah1[mg], ah2[mg], ah3[mg], bhp.x, bhp.y);
                mma_bf16(acc[mg][nt], ah0[mg], ah1[mg], ah2[mg], ah3[mg], blp.x, blp.y);
                mma_bf16(acc[mg][nt], al0[mg], al1[mg], al2[mg], al3[mg], bhp.x, bhp.y);
            }
        }
    }

    // ---- epilogue: bias + relu -> g_H1 ----
    #pragma unroll
    for (int mg = 0; mg < 2; mg++) {
        const int r0g = row0 + rowblk + mg * 16 + g;
        const int r1g = r0g + 8;
        #pragma unroll
        for (int nt = 0; nt < 8; nt++) {
            const int col = colblk + nt * 8 + 2 * i4;
            const float bb0 = b1[col], bb1 = b1[col + 1];
            if (r0g < N1) {
                float v0 = acc[mg][nt][0] + bb0, v1 = acc[mg][nt][1] + bb1;
                *(float2*)(&g_H1[(size_t)r0g * HID + col]) =
                    make_float2(v0 > 0.f ? v0 : 0.f, v1 > 0.f ? v1 : 0.f);
            }
            if (r1g < N1) {
                float v0 = acc[mg][nt][2] + bb0, v1 = acc[mg][nt][3] + bb1;
                *(float2*)(&g_H1[(size_t)r1g * HID + col]) =
                    make_float2(v0 > 0.f ? v0 : 0.f, v1 > 0.f ? v1 : 0.f);
            }
        }
    }
}

// ---------------------------------------------------------------------------
// Kernel 2: G[N1,44] = H1[N1,128] @ W2^T, tensor cores, bf16 hi/lo (R7, good)
// ---------------------------------------------------------------------------
#define NROWS_B 48
__global__ __launch_bounds__(256) void k_logits(
    const float* __restrict__ W2)
{
    __shared__ uint32_t Ah[128 * APITCH];
    __shared__ uint32_t Al[128 * APITCH];
    __shared__ uint32_t Bh[NROWS_B * APITCH];
    __shared__ uint32_t Bl[NROWS_B * APITCH];

    const int tid  = threadIdx.x;
    const int warp = tid >> 5;
    const int lane = tid & 31;
    const int g    = lane >> 2;
    const int i4   = lane & 3;
    const int row0 = blockIdx.x * 128;

    const int lr = tid >> 1;
    const int kh = (tid & 1) * 8;
    const int asidx = lr * APITCH + (kh >> 1);
    const int  grow   = row0 + lr;
    const bool avalid = (grow < N1);

    const int  wr     = tid >> 1;
    const bool bstage = (tid < 96);
    const bool bvalid = bstage && (wr < CLS);

    float acc[6][4];
    #pragma unroll
    for (int t = 0; t < 6; t++)
        #pragma unroll
        for (int j = 0; j < 4; j++) acc[t][j] = 0.f;

    const int ra = (warp * 16 + g) * APITCH;

    #pragma unroll 1
    for (int kc = 0; kc < 8; kc++) {
        const int k0 = kc * 16 + kh;

        float va[8];
        if (avalid) {
            float4 v0 = *(const float4*)(&g_H1[(size_t)grow * HID + k0]);
            float4 v1 = *(const float4*)(&g_H1[(size_t)grow * HID + k0 + 4]);
            va[0]=v0.x; va[1]=v0.y; va[2]=v0.z; va[3]=v0.w;
            va[4]=v1.x; va[5]=v1.y; va[6]=v1.z; va[7]=v1.w;
        } else {
            #pragma unroll
            for (int j = 0; j < 8; j++) va[j] = 0.f;
        }
        float vb[8];
        if (bvalid) {
            float4 w0 = *(const float4*)(&W2[(size_t)wr * HID + k0]);
            float4 w1 = *(const float4*)(&W2[(size_t)wr * HID + k0 + 4]);
            vb[0]=w0.x; vb[1]=w0.y; vb[2]=w0.z; vb[3]=w0.w;
            vb[4]=w1.x; vb[5]=w1.y; vb[6]=w1.z; vb[7]=w1.w;
        } else {
            #pragma unroll
            for (int j = 0; j < 8; j++) vb[j] = 0.f;
        }

        __syncthreads();
        #pragma unroll
        for (int j = 0; j < 4; j++)
            split_pair(va[2*j], va[2*j+1], Ah[asidx + j], Al[asidx + j]);
        if (bstage) {
            #pragma unroll
            for (int j = 0; j < 4; j++)
                split_pair(vb[2*j], vb[2*j+1], Bh[asidx + j], Bl[asidx + j]);
        }
        __syncthreads();

        uint32_t a0h = Ah[ra + i4];
        uint32_t a1h = Ah[ra + 8 * APITCH + i4];
        uint32_t a2h = Ah[ra + i4 + 4];
        uint32_t a3h = Ah[ra + 8 * APITCH + i4 + 4];
        uint32_t a0l = Al[ra + i4];
        uint32_t a1l = Al[ra + 8 * APITCH + i4];
        uint32_t a2l = Al[ra + i4 + 4];
        uint32_t a3l = Al[ra + 8 * APITCH + i4 + 4];

        #pragma unroll
        for (int nt = 0; nt < 6; nt++) {
            const int rb = (nt * 8 + g) * APITCH;
            uint32_t b0h = Bh[rb + i4];
            uint32_t b1h = Bh[rb + i4 + 4];
            uint32_t b0l = Bl[rb + i4];
            uint32_t b1l = Bl[rb + i4 + 4];
            mma_bf16(acc[nt], a0h, a1h, a2h, a3h, b0h, b1h);
            mma_bf16(acc[nt], a0h, a1h, a2h, a3h, b0l, b1l);
            mma_bf16(acc[nt], a0l, a1l, a2l, a3l, b0h, b1h);
        }
    }

    const int r0g = row0 + warp * 16 + g;
    const int r1g = r0g + 8;
    #pragma unroll
    for (int nt = 0; nt < 6; nt++) {
        const int col = nt * 8 + 2 * i4;
        if (col + 1 < CLSP) {
            if (r0g < N1)
                *(float2*)(&g_G[(size_t)r0g * CLSP + col]) =
                    make_float2(acc[nt][0], acc[nt][1]);
            if (r1g < N1)
                *(float2*)(&g_G[(size_t)r1g * CLSP + col]) =
                    make_float2(acc[nt][2], acc[nt][3]);
        }
    }
}

// ---------------------------------------------------------------------------
// Kernel 3: out[n][c] = b2[c] + mean_j G[neigh[n][j]][c]
// ---------------------------------------------------------------------------
__global__ __launch_bounds__(256) void k_gather(
    const int* __restrict__ neigh,
    const float* __restrict__ b2,
    float* __restrict__ out)
{
    const int tid  = threadIdx.x;
    const int grp  = tid >> 6;
    const int lane = tid & 63;
    const int n    = blockIdx.x * 4 + grp;
    if (n >= N2C || lane >= CLS) return;

    const int* nb = neigh + (size_t)n * FAN;
    float s = 0.f;
    #pragma unroll
    for (int j = 0; j < FAN; j++) {
        int idx = nb[j];
        s += g_G[(size_t)idx * CLSP + lane];
    }
    out[(size_t)n * CLS + lane] = fmaf(s, 1.0f / FAN, b2[lane]);
}

// ---------------------------------------------------------------------------
// Launch.  Inputs: features f32, W1 f32, b1 f32, W2 f32, b2 f32,
//                  map1 i32, neigh_idx i32.  Output: f32 [N2*CLS].
// ---------------------------------------------------------------------------
extern "C" void kernel_launch(void* const* d_in, const int* in_sizes, int n_in,
                              void* d_out, int out_size) {
    const float* features = (const float*)d_in[0];
    const float* W1       = (const float*)d_in[1];
    const float* b1       = (const float*)d_in[2];
    const float* W2       = (const float*)d_in[3];
    const float* b2       = (const float*)d_in[4];
    const int*   map1     = (const int*)d_in[5];
    const int*   neigh    = (const int*)d_in[6];
    float*       out      = (float*)d_out;

    static bool attr_done = false;
    if (!attr_done) {
        cudaFuncSetAttribute(k_layer1,
                             cudaFuncAttributeMaxDynamicSharedMemorySize, SMEM_L1);
        attr_done = true;
    }

    const int gridp = (KSTEPS * HID * 8 + 255) / 256;   // 152
    k_prep<<<gridp, 256>>>(W1);

    const int grid1 = (N1 + 127) / 128;                 // 391
    k_layer1<<<grid1, 256, SMEM_L1>>>(features, b1, map1);

    k_logits<<<grid1, 256>>>(W2);

    const int grid3 = (N2C + 3) / 4;                    // 2500
    k_gather<<<grid3, 256>>>(neigh, b2, out);
}

// round 10
// speedup vs baseline: 4.2304x; 1.0521x over previous
#include <cuda_runtime.h>
#include <cuda_bf16.h>
#include <cstdint>

// Problem constants
#define N0    200000
#define N1    50000
#define N2C   10000
#define INF   602
#define HID   128
#define CLS   41
#define CLSP  44
#define FAN   25

#define KSTEPS 38     // 38*16 = 608 >= 602
#define AP     14     // phase-1 A-conv smem pitch (u32 per row)
#define W2ROWS 48     // padded class rows (6 * n8)

// Device scratch
__device__ __align__(16) float g_G[N1 * CLSP];
// W1 pre-converted, k-chunk-major, MMA-pair-permuted: [38][128][8] u32
__device__ __align__(16) uint32_t g_W1kh[KSTEPS * HID * 8];
__device__ __align__(16) uint32_t g_W1kl[KSTEPS * HID * 8];
// W2 pre-converted, k-chunk-major (8 chunks of HID), rows padded to 48
__device__ __align__(16) uint32_t g_W2kh[8 * W2ROWS * 8];
__device__ __align__(16) uint32_t g_W2kl[8 * W2ROWS * 8];

// ---- dynamic smem layout for k_layer1 (byte offsets) ----
// phase 1:
#define AH_OFF   0                         // 2 bufs x 128*AP u32 = 14336 B
#define AL_OFF   14336
#define BH_OFF   28672                     // 3 slots x 4096 B
#define BL_OFF   40960                     // ..53247
// phase 2 (H1 tile overlaps phase-1 region; W2 slabs are disjoint):
#define H1H_OFF  0                         // [8][128][8] u32 = 32768 B
#define H1L_OFF  32768
#define W2H_OFF  65536                     // [8][48][8] u32 = 12288 B
#define W2L_OFF  77824
#define SMEM_L1  90112

// ---------------------------------------------------------------------------
// helpers
// ---------------------------------------------------------------------------
__device__ __forceinline__ void mma_bf16(float c[4],
                                         uint32_t a0, uint32_t a1, uint32_t a2, uint32_t a3,
                                         uint32_t b0, uint32_t b1)
{
    asm volatile(
        "mma.sync.aligned.m16n8k16.row.col.f32.bf16.bf16.f32 "
        "{%0,%1,%2,%3}, {%4,%5,%6,%7}, {%8,%9}, {%0,%1,%2,%3};\n"
        : "+f"(c[0]), "+f"(c[1]), "+f"(c[2]), "+f"(c[3])
        : "r"(a0), "r"(a1), "r"(a2), "r"(a3), "r"(b0), "r"(b1));
}

__device__ __forceinline__ void split_pair(float x0, float x1,
                                           uint32_t& hi, uint32_t& lo)
{
    __nv_bfloat162 h2 = __floats2bfloat162_rn(x0, x1);
    float2 hf = __bfloat1622float2(h2);
    __nv_bfloat162 l2 = __floats2bfloat162_rn(x0 - hf.x, x1 - hf.y);
    hi = *reinterpret_cast<uint32_t*>(&h2);
    lo = *reinterpret_cast<uint32_t*>(&l2);
}

__device__ __forceinline__ void cp16(uint32_t dst, const void* src) {
    asm volatile("cp.async.cg.shared.global [%0], [%1], 16;\n"
                 :: "r"(dst), "l"(src));
}
#define CP_COMMIT() asm volatile("cp.async.commit_group;\n" ::: "memory")
#define CP_WAIT(n)  asm volatile("cp.async.wait_group %0;\n" :: "n"(n) : "memory")

// ---------------------------------------------------------------------------
// Kernel 0: W1 and W2 -> bf16 hi/lo, k-chunk-major, MMA-pair permutation.
// perm: position c = (i<4) ? 2i : 2(i-4)+1 for pair i (k = 16p + 2i)
// ---------------------------------------------------------------------------
#define PREP_W1 (KSTEPS * HID * 8)     // 38912
#define PREP_W2 (8 * W2ROWS * 8)       // 3072
__global__ __launch_bounds__(256) void k_prep(const float* __restrict__ W1,
                                              const float* __restrict__ W2)
{
    int idx = blockIdx.x * 256 + threadIdx.x;
    if (idx < PREP_W1) {
        const int p   = idx >> 10;
        const int rem = idx & 1023;
        const int r   = rem >> 3;
        const int i   = rem & 7;
        const int c   = (i < 4) ? (2 * i) : (2 * (i - 4) + 1);
        const int k0  = p * 16 + 2 * i;
        float x0 = (k0     < INF) ? W1[(size_t)r * INF + k0]     : 0.f;
        float x1 = (k0 + 1 < INF) ? W1[(size_t)r * INF + k0 + 1] : 0.f;
        uint32_t h, l;
        split_pair(x0, x1, h, l);
        const int didx = (p * HID + r) * 8 + c;
        g_W1kh[didx] = h;
        g_W1kl[didx] = l;
    } else if (idx < PREP_W1 + PREP_W2) {
        const int j   = idx - PREP_W1;
        const int p   = j / (W2ROWS * 8);
        const int rem = j % (W2ROWS * 8);
        const int r   = rem >> 3;
        const int i   = rem & 7;
        const int c   = (i < 4) ? (2 * i) : (2 * (i - 4) + 1);
        const int k0  = p * 16 + 2 * i;          // < 128 always
        float x0 = (r < CLS) ? W2[(size_t)r * HID + k0]     : 0.f;
        float x1 = (r < CLS) ? W2[(size_t)r * HID + k0 + 1] : 0.f;
        uint32_t h, l;
        split_pair(x0, x1, h, l);
        const int didx = (p * W2ROWS + r) * 8 + c;
        g_W2kh[didx] = h;
        g_W2kl[didx] = l;
    }
}

// ---------------------------------------------------------------------------
// Kernel 1 (fused): phase 1: H1 = relu(features[map1] @ W1^T + b1) (regs)
//                   phase 2: G = H1 @ W2^T  -> g_G   (same CTA, via smem)
// ---------------------------------------------------------------------------
__global__ __launch_bounds__(256, 2) void k_layer1(
    const float* __restrict__ features,
    const float* __restrict__ b1,
    const int* __restrict__ map1)
{
    extern __shared__ char smem[];
    const uint32_t sbase = (uint32_t)__cvta_generic_to_shared(smem);
    uint32_t* AHs = (uint32_t*)(smem + AH_OFF);
    uint32_t* ALs = (uint32_t*)(smem + AL_OFF);
    const uint32_t* BHs = (const uint32_t*)(smem + BH_OFF);
    const uint32_t* BLs = (const uint32_t*)(smem + BL_OFF);
    uint32_t* H1h = (uint32_t*)(smem + H1H_OFF);
    uint32_t* H1l = (uint32_t*)(smem + H1L_OFF);
    uint32_t* W2h = (uint32_t*)(smem + W2H_OFF);
    uint32_t* W2l = (uint32_t*)(smem + W2L_OFF);

    const int tid  = threadIdx.x;
    const int warp = tid >> 5;
    const int lane = tid & 31;
    const int g    = lane >> 2;
    const int i4   = lane & 3;
    const int q    = lane >> 3;
    const int o    = lane & 7;
    const int co   = (o < 4) ? (2 * o) : (2 * (o - 4) + 1);

    const int row0 = blockIdx.x * 128;

    // preload W2 slabs into disjoint smem region (used in phase 2)
    for (int i = tid; i < PREP_W2; i += 256) {
        W2h[i] = g_W2kh[i];
        W2l[i] = g_W2kl[i];
    }

    // 4 staged rows per thread: R_j = warp*16 + 4j + q
    const float* aptr[4];
    bool rv[4];
    int  Rl[4];
    #pragma unroll
    for (int j = 0; j < 4; j++) {
        const int R  = warp * 16 + 4 * j + q;
        const int gr = row0 + R;
        Rl[j] = R;
        rv[j] = (gr < N1);
        const int src = rv[j] ? map1[gr] : 0;
        aptr[j] = features + (size_t)src * INF + 2 * o;
    }

    float2 cur[4];
    auto ldA = [&](int p) {
        const bool kv = (16 * p + 2 * o + 1) < INF;
        #pragma unroll
        for (int j = 0; j < 4; j++) {
            cur[j] = (rv[j] && kv) ? *(const float2*)(aptr[j] + 16 * p)
                                   : make_float2(0.f, 0.f);
        }
    };

    auto issueB = [&](int p) {
        const int slot = p % 3;
        cp16(sbase + BH_OFF + slot * 4096 + tid * 16, g_W1kh + p * 1024 + tid * 4);
        cp16(sbase + BL_OFF + slot * 4096 + tid * 16, g_W1kl + p * 1024 + tid * 4);
        CP_COMMIT();
    };

    ldA(0);
    issueB(0);
    issueB(1);

    float acc[2][8][4];
    #pragma unroll
    for (int mg = 0; mg < 2; mg++)
        #pragma unroll
        for (int nt = 0; nt < 8; nt++)
            #pragma unroll
            for (int j = 0; j < 4; j++) acc[mg][nt][j] = 0.f;

    const int rowblk = (warp & 3) * 32;
    const int colblk = (warp >> 2) * 64;

    #pragma unroll 1
    for (int s = 0; s < KSTEPS; s++) {
        uint32_t* ah = AHs + (s & 1) * (128 * AP);
        uint32_t* al = ALs + (s & 1) * (128 * AP);
        #pragma unroll
        for (int j = 0; j < 4; j++) {
            uint32_t h, l;
            split_pair(cur[j].x, cur[j].y, h, l);
            ah[Rl[j] * AP + co] = h;
            al[Rl[j] * AP + co] = l;
        }
        if (s + 1 < KSTEPS) ldA(s + 1);

        CP_WAIT(1);
        __syncthreads();
        if (s + 2 < KSTEPS) issueB(s + 2);

        const uint32_t* bh = BHs + (s % 3) * 1024;
        const uint32_t* bl = BLs + (s % 3) * 1024;

        uint32_t ah0[2], ah1[2], ah2[2], ah3[2];
        uint32_t al0[2], al1[2], al2[2], al3[2];
        #pragma unroll
        for (int mg = 0; mg < 2; mg++) {
            const int r = rowblk + mg * 16 + g;
            uint2 h0 = *(const uint2*)&ah[r * AP + 2 * i4];
            uint2 h1 = *(const uint2*)&ah[(r + 8) * AP + 2 * i4];
            uint2 l0 = *(const uint2*)&al[r * AP + 2 * i4];
            uint2 l1 = *(const uint2*)&al[(r + 8) * AP + 2 * i4];
            ah0[mg] = h0.x; ah2[mg] = h0.y; ah1[mg] = h1.x; ah3[mg] = h1.y;
            al0[mg] = l0.x; al2[mg] = l0.y; al1[mg] = l1.x; al3[mg] = l1.y;
        }

        #pragma unroll
        for (int nt = 0; nt < 8; nt++) {
            const int rb = (colblk + nt * 8 + g) * 8 + 2 * i4;
            uint2 bhp = *(const uint2*)&bh[rb];
            uint2 blp = *(const uint2*)&bl[rb];
            #pragma unroll
            for (int mg = 0; mg < 2; mg++) {
                mma_bf16(acc[mg][nt], ah0[mg], ah1[mg], ah2[mg], ah3[mg], bhp.x, bhp.y);
                mma_bf16(acc[mg][nt], ah0[mg], ah1[mg], ah2[mg], ah3[mg], blp.x, blp.y);
                mma_bf16(acc[mg][nt], al0[mg], al1[mg], al2[mg], al3[mg], bhp.x, bhp.y);
            }
        }
    }

    // ---- phase-1 epilogue: bias + relu, split to bf16, store chunk-major ----
    __syncthreads();   // all phase-1 smem reads done before overwrite
    #pragma unroll
    for (int mg = 0; mg < 2; mg++) {
        const int r0 = rowblk + mg * 16 + g;
        const int r1 = r0 + 8;
        #pragma unroll
        for (int nt = 0; nt < 8; nt++) {
            const int col = colblk + nt * 8 + 2 * i4;
            const int kc  = col >> 4;
            const int ii  = ((col & 15) >> 1);
            const int cw  = (ii < 4) ? (2 * ii) : (2 * (ii - 4) + 1);
            const float bb0 = b1[col], bb1 = b1[col + 1];
            {
                float v0 = acc[mg][nt][0] + bb0; v0 = v0 > 0.f ? v0 : 0.f;
                float v1 = acc[mg][nt][1] + bb1; v1 = v1 > 0.f ? v1 : 0.f;
                uint32_t h, l;
                split_pair(v0, v1, h, l);
                H1h[(kc * 128 + r0) * 8 + cw] = h;
                H1l[(kc * 128 + r0) * 8 + cw] = l;
            }
            {
                float v0 = acc[mg][nt][2] + bb0; v0 = v0 > 0.f ? v0 : 0.f;
                float v1 = acc[mg][nt][3] + bb1; v1 = v1 > 0.f ? v1 : 0.f;
                uint32_t h, l;
                split_pair(v0, v1, h, l);
                H1h[(kc * 128 + r1) * 8 + cw] = h;
                H1l[(kc * 128 + r1) * 8 + cw] = l;
            }
        }
    }
    __syncthreads();

    // ---- phase 2: G tile = H1 tile @ W2^T ----
    float gacc[6][4];
    #pragma unroll
    for (int t = 0; t < 6; t++)
        #pragma unroll
        for (int j = 0; j < 4; j++) gacc[t][j] = 0.f;

    const int r2 = warp * 16 + g;

    #pragma unroll
    for (int kc = 0; kc < 8; kc++) {
        const int ab = (kc * 128 + r2) * 8;
        uint2 h0 = *(const uint2*)&H1h[ab + 2 * i4];
        uint2 h1 = *(const uint2*)&H1h[ab + 64 + 2 * i4];   // row +8
        uint2 l0 = *(const uint2*)&H1l[ab + 2 * i4];
        uint2 l1 = *(const uint2*)&H1l[ab + 64 + 2 * i4];
        const uint32_t a0h = h0.x, a2h = h0.y, a1h = h1.x, a3h = h1.y;
        const uint32_t a0l = l0.x, a2l = l0.y, a1l = l1.x, a3l = l1.y;

        #pragma unroll
        for (int nt = 0; nt < 6; nt++) {
            const int rb = (kc * W2ROWS + nt * 8 + g) * 8 + 2 * i4;
            uint2 bhp = *(const uint2*)&W2h[rb];
            uint2 blp = *(const uint2*)&W2l[rb];
            mma_bf16(gacc[nt], a0h, a1h, a2h, a3h, bhp.x, bhp.y);
            mma_bf16(gacc[nt], a0h, a1h, a2h, a3h, blp.x, blp.y);
            mma_bf16(gacc[nt], a0l, a1l, a2l, a3l, bhp.x, bhp.y);
        }
    }

    // ---- phase-2 epilogue -> g_G ----
    const int r0g = row0 + r2;
    const int r1g = r0g + 8;
    #pragma unroll
    for (int nt = 0; nt < 6; nt++) {
        const int col = nt * 8 + 2 * i4;
        if (col + 1 < CLSP) {
            if (r0g < N1)
                *(float2*)(&g_G[(size_t)r0g * CLSP + col]) =
                    make_float2(gacc[nt][0], gacc[nt][1]);
            if (r1g < N1)
                *(float2*)(&g_G[(size_t)r1g * CLSP + col]) =
                    make_float2(gacc[nt][2], gacc[nt][3]);
        }
    }
}

// ---------------------------------------------------------------------------
// Kernel 2: out[n][c] = b2[c] + mean_j G[neigh[n][j]][c]
// One warp per seed; lanes 0..10 hold the 44-col row as float4.
// ---------------------------------------------------------------------------
__global__ __launch_bounds__(256) void k_gather(
    const int* __restrict__ neigh,
    const float* __restrict__ b2,
    float* __restrict__ out)
{
    const int warp = threadIdx.x >> 5;
    const int lane = threadIdx.x & 31;
    const int n    = blockIdx.x * 8 + warp;          // grid covers N2C exactly

    const int nbv = (lane < FAN) ? neigh[(size_t)n * FAN + lane] : 0;

    float4 a4 = make_float4(0.f, 0.f, 0.f, 0.f);
    const float4* G4 = (const float4*)g_G;
    #pragma unroll
    for (int j = 0; j < FAN; j++) {
        const int idx = __shfl_sync(0xffffffffu, nbv, j);
        if (lane < 11) {
            float4 v = G4[(size_t)idx * 11 + lane];
            a4.x += v.x; a4.y += v.y; a4.z += v.z; a4.w += v.w;
        }
    }
    if (lane < 11) {
        const float inv = 1.0f / FAN;
        float vals[4] = {a4.x, a4.y, a4.z, a4.w};
        #pragma unroll
        for (int e = 0; e < 4; e++) {
            const int c = lane * 4 + e;
            if (c < CLS)
                out[(size_t)n * CLS + c] = fmaf(vals[e], inv, b2[c]);
        }
    }
}

// ---------------------------------------------------------------------------
// Launch.  Inputs: features f32, W1 f32, b1 f32, W2 f32, b2 f32,
//                  map1 i32, neigh_idx i32.  Output: f32 [N2*CLS].
// ---------------------------------------------------------------------------
extern "C" void kernel_launch(void* const* d_in, const int* in_sizes, int n_in,
                              void* d_out, int out_size) {
    const float* features = (const float*)d_in[0];
    const float* W1       = (const float*)d_in[1];
    const float* b1       = (const float*)d_in[2];
    const float* W2       = (const float*)d_in[3];
    const float* b2       = (const float*)d_in[4];
    const int*   map1     = (const int*)d_in[5];
    const int*   neigh    = (const int*)d_in[6];
    float*       out      = (float*)d_out;

    static bool attr_done = false;
    if (!attr_done) {
        cudaFuncSetAttribute(k_layer1,
                             cudaFuncAttributeMaxDynamicSharedMemorySize, SMEM_L1);
        attr_done = true;
    }

    const int gridp = (PREP_W1 + PREP_W2 + 255) / 256;   // 164
    k_prep<<<gridp, 256>>>(W1, W2);

    const int grid1 = (N1 + 127) / 128;                  // 391
    k_layer1<<<grid1, 256, SMEM_L1>>>(features, b1, map1);

    k_gather<<<N2C / 8, 256>>>(neigh, b2, out);          // 1250 blocks
}